// round 5
// baseline (speedup 1.0000x reference)
#include <cuda_runtime.h>

// Problem constants
#define WN      343        // tokens per window
#define CDIM    96
#define NHEADS  3
#define HD      32
#define NB      512        // total windows
#define NWIN    64         // mask batch
#define BH      (NB*NHEADS)        // 1536
#define RTOT    (NB*WN)            // 175616 rows

#define LOG2E 1.4426950408889634f

typedef unsigned long long ull_t;

// ---- packed f32x2 helpers (Blackwell: full 128-lane fp32 rate) -------------
__device__ __forceinline__ ull_t dup2(float a) {
    ull_t r; asm("mov.b64 %0, {%1, %1};" : "=l"(r) : "f"(a)); return r;
}
__device__ __forceinline__ ull_t fma2(ull_t a, ull_t b, ull_t c) {
    ull_t d; asm("fma.rn.f32x2 %0, %1, %2, %3;" : "=l"(d) : "l"(a), "l"(b), "l"(c)); return d;
}
__device__ __forceinline__ ull_t add2(ull_t a, ull_t b) {
    ull_t d; asm("add.rn.f32x2 %0, %1, %2;" : "=l"(d) : "l"(a), "l"(b)); return d;
}
__device__ __forceinline__ ull_t mul2(ull_t a, ull_t b) {
    ull_t d; asm("mul.rn.f32x2 %0, %1, %2;" : "=l"(d) : "l"(a), "l"(b)); return d;
}
__device__ __forceinline__ void unpack2(ull_t v, float& lo, float& hi) {
    asm("mov.b64 {%0, %1}, %2;" : "=f"(lo), "=f"(hi) : "l"(v));
}
__device__ __forceinline__ float ex2f(float x) {
    float r; asm("ex2.approx.ftz.f32 %0, %1;" : "=f"(r) : "f"(x)); return r;
}

// Scratch (static device arrays: allocation-free). biasT/maskT padded by 3*WN
// floats so the j+2 prefetch in attn never reads out of bounds.
__device__ float g_q[BH*WN*HD];
__device__ float g_k[BH*WN*HD];
__device__ float g_v[BH*WN*HD];
__device__ float g_o[BH*WN*HD];
__device__ float g_biasT[NHEADS*WN*WN + 3*WN];  // ((bias[h][j][i] - 11) * LOG2E)
__device__ float g_maskT[NWIN*WN*WN + 3*WN];    // mask[w][j][i] * LOG2E

// ---------------------------------------------------------------------------
// Kernel A: qkv = x @ Wqkv^T + bqkv, scattered to g_q/g_k/g_v [B][H][N][32]
// 64 rows/block, 576 threads = 72 colgroups(4c) x 8 rowgroups(8r), row-packed.
// ---------------------------------------------------------------------------
#define QKV_WPAD 292
#define XT_PAD   68
__global__ __launch_bounds__(576) void qkv_kernel(
    const float* __restrict__ x, const float* __restrict__ Wqkv,
    const float* __restrict__ bqkv)
{
    extern __shared__ float sm[];
    float* Wt  = sm;                     // [96][292] : Wt[k][c] = Wqkv[c][k]
    float* xsT = sm + 96*QKV_WPAD;       // [96][68]  : xsT[k][row]
    const int tid = threadIdx.x;

    for (int idx = tid; idx < 288*96; idx += 576) {
        int c = idx / 96, k = idx - c*96;
        Wt[k*QKV_WPAD + c] = Wqkv[idx];
    }
    const int r0 = blockIdx.x * 64;
    for (int idx = tid; idx < 64*96; idx += 576) {
        int row = idx / 96, k = idx - row*96;
        xsT[k*XT_PAD + row] = x[(r0 + row)*96 + k];
    }
    __syncthreads();

    const int cg = tid % 72;
    const int rg = tid / 72;
    const int c0 = cg * 4;
    const int i0 = rg * 8;

    ull_t acc[4][4];
#pragma unroll
    for (int rp = 0; rp < 4; rp++)
#pragma unroll
        for (int c = 0; c < 4; c++) acc[rp][c] = 0ull;

#pragma unroll 4
    for (int k = 0; k < 96; k++) {
        float4 w = *(const float4*)(Wt + k*QKV_WPAD + c0);
        ull_t wd0 = dup2(w.x), wd1 = dup2(w.y), wd2 = dup2(w.z), wd3 = dup2(w.w);
        ulonglong2 xa = *(const ulonglong2*)(xsT + k*XT_PAD + i0);
        ulonglong2 xb = *(const ulonglong2*)(xsT + k*XT_PAD + i0 + 4);
        acc[0][0] = fma2(xa.x, wd0, acc[0][0]);
        acc[0][1] = fma2(xa.x, wd1, acc[0][1]);
        acc[0][2] = fma2(xa.x, wd2, acc[0][2]);
        acc[0][3] = fma2(xa.x, wd3, acc[0][3]);
        acc[1][0] = fma2(xa.y, wd0, acc[1][0]);
        acc[1][1] = fma2(xa.y, wd1, acc[1][1]);
        acc[1][2] = fma2(xa.y, wd2, acc[1][2]);
        acc[1][3] = fma2(xa.y, wd3, acc[1][3]);
        acc[2][0] = fma2(xb.x, wd0, acc[2][0]);
        acc[2][1] = fma2(xb.x, wd1, acc[2][1]);
        acc[2][2] = fma2(xb.x, wd2, acc[2][2]);
        acc[2][3] = fma2(xb.x, wd3, acc[2][3]);
        acc[3][0] = fma2(xb.y, wd0, acc[3][0]);
        acc[3][1] = fma2(xb.y, wd1, acc[3][1]);
        acc[3][2] = fma2(xb.y, wd2, acc[3][2]);
        acc[3][3] = fma2(xb.y, wd3, acc[3][3]);
    }

    float4 bb = *(const float4*)(bqkv + c0);
    const int seg = c0 / 96;              // 0=q 1=k 2=v
    const int cc  = c0 - seg*96;
    const int h   = cc >> 5;
    const int d0  = cc & 31;
    float* dst = (seg == 0) ? g_q : ((seg == 1) ? g_k : g_v);
#pragma unroll
    for (int rp = 0; rp < 4; rp++) {
        float e0[4], e1[4];
#pragma unroll
        for (int c = 0; c < 4; c++) unpack2(acc[rp][c], e0[c], e1[c]);
        int ra = r0 + i0 + 2*rp;
        int ba = ra / WN, na = ra - ba*WN;
        float4 ov;
        ov.x = e0[0]+bb.x; ov.y = e0[1]+bb.y; ov.z = e0[2]+bb.z; ov.w = e0[3]+bb.w;
        *(float4*)(dst + (((ba*NHEADS + h)*WN) + na)*HD + d0) = ov;
        int rb = ra + 1;
        int bb2 = rb / WN, nb = rb - bb2*WN;
        ov.x = e1[0]+bb.x; ov.y = e1[1]+bb.y; ov.z = e1[2]+bb.z; ov.w = e1[3]+bb.w;
        *(float4*)(dst + (((bb2*NHEADS + h)*WN) + nb)*HD + d0) = ov;
    }
}

// ---------------------------------------------------------------------------
// Kernel B: in-place L2-normalize k; normalize+scale q (scale folds in LOG2E).
// ---------------------------------------------------------------------------
__global__ void norm_kernel(const float* __restrict__ logit_scale)
{
    int row = blockIdx.x*256 + threadIdx.x;
    if (row >= BH*WN) return;
    int h = (row / WN) % NHEADS;
    float scale = expf(fminf(logit_scale[h], 4.6051702f)) * LOG2E;
    float4* qp = (float4*)(g_q + (size_t)row*HD);
    float4* kp = (float4*)(g_k + (size_t)row*HD);
    float4 qv[8], kv[8];
    float sq = 0.f, skk = 0.f;
#pragma unroll
    for (int m = 0; m < 8; m++) {
        qv[m] = qp[m]; kv[m] = kp[m];
        sq  += qv[m].x*qv[m].x + qv[m].y*qv[m].y + qv[m].z*qv[m].z + qv[m].w*qv[m].w;
        skk += kv[m].x*kv[m].x + kv[m].y*kv[m].y + kv[m].z*kv[m].z + kv[m].w*kv[m].w;
    }
    float rq = rsqrtf(fmaxf(sq,  1e-24f)) * scale;
    float rk = rsqrtf(fmaxf(skk, 1e-24f));
#pragma unroll
    for (int m = 0; m < 8; m++) {
        float4 a = qv[m], c = kv[m];
        a.x *= rq; a.y *= rq; a.z *= rq; a.w *= rq;
        c.x *= rk; c.y *= rk; c.z *= rk; c.w *= rk;
        qp[m] = a; kp[m] = c;
    }
}

// ---------------------------------------------------------------------------
// Kernel C: tiled transpose prep, pre-multiplied by LOG2E.
// ---------------------------------------------------------------------------
__global__ void prep_kernel(const float* __restrict__ mask,
                            const float* __restrict__ bias_table,
                            const int* __restrict__ rpi)
{
    __shared__ float tile[32][33];
    const int j0 = blockIdx.x*32;
    const int i0 = blockIdx.y*32;
    const int z  = blockIdx.z;
    const int tx = threadIdx.x, ty = threadIdx.y;
    if (z < NWIN) {
        const float* src = mask + (size_t)z*WN*WN;
#pragma unroll
        for (int s = 0; s < 32; s += 8) {
            int i = i0 + ty + s, j = j0 + tx;
            tile[ty+s][tx] = (i < WN && j < WN) ? src[i*WN + j]*LOG2E : 0.f;
        }
        __syncthreads();
        float* dst = g_maskT + (size_t)z*WN*WN;
#pragma unroll
        for (int s = 0; s < 32; s += 8) {
            int j = j0 + ty + s, i = i0 + tx;
            if (i < WN && j < WN) dst[j*WN + i] = tile[tx][ty+s];
        }
    } else {
        const int h = z - NWIN;
#pragma unroll
        for (int s = 0; s < 32; s += 8) {
            int i = i0 + ty + s, j = j0 + tx;
            tile[ty+s][tx] = (i < WN && j < WN)
                ? ((bias_table[rpi[i*WN + j]*NHEADS + h] - 11.0f) * LOG2E) : 0.f;
        }
        __syncthreads();
        float* dst = g_biasT + (size_t)h*WN*WN;
#pragma unroll
        for (int s = 0; s < 32; s += 8) {
            int j = j0 + ty + s, i = i0 + tx;
            if (i < WN && j < WN) dst[j*WN + i] = tile[tx][ty+s];
        }
    }
}

// ---------------------------------------------------------------------------
// Kernel D: fused attention, one CTA per (window, head), 768 threads.
// Each query row is handled by a PAIR of threads (16 head-dims each);
// partial scores combine via shfl.xor(lane^1). 24 warps/SM, ~70 regs/thread.
// Fixed softmax max (folded into biasT) -> no online rescaling.
// ---------------------------------------------------------------------------
__global__ __launch_bounds__(768, 1) void attn_kernel()
{
    extern __shared__ float sm[];
    float* sK = sm;                 // [343][32]
    float* sV = sm + WN*HD;         // [343][32]
    const int t  = threadIdx.x;
    const int bh = blockIdx.x;
    const int b  = bh / NHEADS;
    const int h  = bh - b*NHEADS;
    const int w  = b & (NWIN - 1);
    const float* qb = g_q + (size_t)bh*WN*HD;
    const float* kb = g_k + (size_t)bh*WN*HD;
    const float* vb = g_v + (size_t)bh*WN*HD;

    for (int idx = t; idx < WN*HD/4; idx += 768) {
        ((float4*)sK)[idx] = ((const float4*)kb)[idx];
        ((float4*)sV)[idx] = ((const float4*)vb)[idx];
    }

    const int r    = t >> 1;        // row slot 0..383
    const int half = t & 1;         // which 16 head-dims
    const bool act = (r < WN);
    const int i    = act ? r : 0;
    const int doff = half * 16;

    // q: 16 floats = 4x ulonglong2 -> 8 packed lanes
    ull_t qp[8];
    {
        const ulonglong2* qs = (const ulonglong2*)(qb + i*HD + doff);
#pragma unroll
        for (int m = 0; m < 4; m++) {
            ulonglong2 v = qs[m];
            qp[2*m] = v.x; qp[2*m+1] = v.y;
        }
    }
    __syncthreads();

    // fully-idle warps (rows >= 352) exit after the barrier
    if ((t >> 5) >= 22) return;

    const float* bias_p = g_biasT + (size_t)h*WN*WN + i;
    const float* mask_p = g_maskT + (size_t)w*WN*WN + i;

    ull_t o[8];
#pragma unroll
    for (int m = 0; m < 8; m++) o[m] = 0ull;
    float l = 0.f;

    // j and j+1 bias+mask prefetched; rolling pointers sit at j+2
    float bmA = __ldg(bias_p)      + __ldg(mask_p);
    float bmB = __ldg(bias_p + WN) + __ldg(mask_p + WN);
    const float* pA = bias_p + 2*WN;
    const float* pM = mask_p + 2*WN;

    for (int j = 0; j < WN; j++) {
        const ulonglong2* kp = (const ulonglong2*)(sK + j*HD + doff);
        ull_t a0 = 0ull, a1 = 0ull, a2 = 0ull, a3 = 0ull;
        {
            ulonglong2 k0 = kp[0], k1 = kp[1], k2 = kp[2], k3 = kp[3];
            a0 = fma2(qp[0], k0.x, a0);
            a1 = fma2(qp[1], k0.y, a1);
            a2 = fma2(qp[2], k1.x, a2);
            a3 = fma2(qp[3], k1.y, a3);
            a0 = fma2(qp[4], k2.x, a0);
            a1 = fma2(qp[5], k2.y, a1);
            a2 = fma2(qp[6], k3.x, a2);
            a3 = fma2(qp[7], k3.y, a3);
        }
        a0 = add2(a0, a1); a2 = add2(a2, a3); a0 = add2(a0, a2);
        float lo, hi; unpack2(a0, lo, hi);
        float s = lo + hi;
        s += __shfl_xor_sync(0xffffffffu, s, 1);

        float p = ex2f(s + bmA);
        bmA = bmB;
        bmB = __ldg(pA) + __ldg(pM);    // j+2 (padded arrays)
        pA += WN; pM += WN;

        l += p;
        ull_t pd = dup2(p);
        const ulonglong2* vp = (const ulonglong2*)(sV + j*HD + doff);
        ulonglong2 v0 = vp[0], v1 = vp[1], v2 = vp[2], v3 = vp[3];
        o[0] = fma2(pd, v0.x, o[0]);
        o[1] = fma2(pd, v0.y, o[1]);
        o[2] = fma2(pd, v1.x, o[2]);
        o[3] = fma2(pd, v1.y, o[3]);
        o[4] = fma2(pd, v2.x, o[4]);
        o[5] = fma2(pd, v2.y, o[5]);
        o[6] = fma2(pd, v3.x, o[6]);
        o[7] = fma2(pd, v3.y, o[7]);
    }

    if (act) {
        float* ob = g_o + (size_t)bh*WN*HD + i*HD + doff;
        ull_t invd = dup2(1.f / l);
        ulonglong2* os = (ulonglong2*)ob;
#pragma unroll
        for (int m = 0; m < 4; m++) {
            ulonglong2 rr;
            rr.x = mul2(o[2*m],   invd);
            rr.y = mul2(o[2*m+1], invd);
            os[m] = rr;
        }
    }
}

// ---------------------------------------------------------------------------
// Kernel E: out = gathered(g_o) @ Wproj^T + bproj (row-packed f32x2)
// ---------------------------------------------------------------------------
#define PJ_WPAD 100
__global__ __launch_bounds__(192) void proj_kernel(
    const float* __restrict__ Wproj, const float* __restrict__ bproj,
    float* __restrict__ out)
{
    extern __shared__ float sm[];
    float* Wt  = sm;                   // [96][100]
    float* xsT = sm + 96*PJ_WPAD;      // [96][68] : xsT[f][row]
    const int tid = threadIdx.x;
    for (int idx = tid; idx < 96*96; idx += 192) {
        int c = idx / 96, k = idx - c*96;
        Wt[k*PJ_WPAD + c] = Wproj[idx];
    }
    const int r0 = blockIdx.x*64;
    for (int idx = tid; idx < 64*96; idx += 192) {
        int row = idx / 96, f = idx - row*96;
        int r = r0 + row;
        int b = r / WN, n = r - b*WN;
        int h = f >> 5, d = f & 31;
        xsT[f*XT_PAD + row] = g_o[(((b*NHEADS + h)*WN) + n)*HD + d];
    }
    __syncthreads();

    const int cg = tid % 24, rg = tid / 24;
    const int c0 = cg*4;
    const int i0 = rg*8;

    ull_t acc[4][4];
#pragma unroll
    for (int rp = 0; rp < 4; rp++)
#pragma unroll
        for (int c = 0; c < 4; c++) acc[rp][c] = 0ull;

#pragma unroll 4
    for (int k = 0; k < 96; k++) {
        float4 w = *(const float4*)(Wt + k*PJ_WPAD + c0);
        ull_t wd0 = dup2(w.x), wd1 = dup2(w.y), wd2 = dup2(w.z), wd3 = dup2(w.w);
        ulonglong2 xa = *(const ulonglong2*)(xsT + k*XT_PAD + i0);
        ulonglong2 xb = *(const ulonglong2*)(xsT + k*XT_PAD + i0 + 4);
        acc[0][0] = fma2(xa.x, wd0, acc[0][0]);
        acc[0][1] = fma2(xa.x, wd1, acc[0][1]);
        acc[0][2] = fma2(xa.x, wd2, acc[0][2]);
        acc[0][3] = fma2(xa.x, wd3, acc[0][3]);
        acc[1][0] = fma2(xa.y, wd0, acc[1][0]);
        acc[1][1] = fma2(xa.y, wd1, acc[1][1]);
        acc[1][2] = fma2(xa.y, wd2, acc[1][2]);
        acc[1][3] = fma2(xa.y, wd3, acc[1][3]);
        acc[2][0] = fma2(xb.x, wd0, acc[2][0]);
        acc[2][1] = fma2(xb.x, wd1, acc[2][1]);
        acc[2][2] = fma2(xb.x, wd2, acc[2][2]);
        acc[2][3] = fma2(xb.x, wd3, acc[2][3]);
        acc[3][0] = fma2(xb.y, wd0, acc[3][0]);
        acc[3][1] = fma2(xb.y, wd1, acc[3][1]);
        acc[3][2] = fma2(xb.y, wd2, acc[3][2]);
        acc[3][3] = fma2(xb.y, wd3, acc[3][3]);
    }

    float4 bb = *(const float4*)(bproj + c0);
#pragma unroll
    for (int rp = 0; rp < 4; rp++) {
        float e0[4], e1[4];
#pragma unroll
        for (int c = 0; c < 4; c++) unpack2(acc[rp][c], e0[c], e1[c]);
        int ra = r0 + i0 + 2*rp;
        float4 ov;
        ov.x = e0[0]+bb.x; ov.y = e0[1]+bb.y; ov.z = e0[2]+bb.z; ov.w = e0[3]+bb.w;
        *(float4*)(out + (size_t)ra*CDIM + c0) = ov;
        ov.x = e1[0]+bb.x; ov.y = e1[1]+bb.y; ov.z = e1[2]+bb.z; ov.w = e1[3]+bb.w;
        *(float4*)(out + (size_t)(ra+1)*CDIM + c0) = ov;
    }
}

// ---------------------------------------------------------------------------
extern "C" void kernel_launch(void* const* d_in, const int* in_sizes, int n_in,
                              void* d_out, int out_size)
{
    (void)in_sizes; (void)n_in; (void)out_size;
    const float* x           = (const float*)d_in[0];
    const float* mask        = (const float*)d_in[1];
    const float* Wqkv        = (const float*)d_in[2];
    const float* bqkv        = (const float*)d_in[3];
    const float* Wproj       = (const float*)d_in[4];
    const float* bproj       = (const float*)d_in[5];
    const float* logit_scale = (const float*)d_in[6];
    const float* bias_table  = (const float*)d_in[7];
    const int*   rpi         = (const int*)d_in[8];
    float* out = (float*)d_out;

    const int smA = (96*QKV_WPAD + 96*XT_PAD) * 4;   // 138240 B
    const int smD = 2*WN*HD*4;                        // 87808 B
    const int smE = (96*PJ_WPAD + 96*XT_PAD) * 4;    // 64512 B
    cudaFuncSetAttribute(qkv_kernel,  cudaFuncAttributeMaxDynamicSharedMemorySize, smA);
    cudaFuncSetAttribute(attn_kernel, cudaFuncAttributeMaxDynamicSharedMemorySize, smD);
    cudaFuncSetAttribute(proj_kernel, cudaFuncAttributeMaxDynamicSharedMemorySize, smE);

    qkv_kernel<<<RTOT/64, 576, smA>>>(x, Wqkv, bqkv);
    prep_kernel<<<dim3(11, 11, NWIN + NHEADS), dim3(32, 8)>>>(mask, bias_table, rpi);
    norm_kernel<<<(BH*WN + 255)/256, 256>>>(logit_scale);
    attn_kernel<<<BH, 768, smD>>>();
    proj_kernel<<<RTOT/64, 192, smE>>>(Wproj, bproj, out);
}

// round 7
// speedup vs baseline: 1.0689x; 1.0689x over previous
#include <cuda_runtime.h>

// Problem constants
#define WN      343        // tokens per window
#define CDIM    96
#define NHEADS  3
#define HD      32
#define NB      512        // total windows
#define NWIN    64         // mask batch
#define BH      (NB*NHEADS)        // 1536
#define RTOT    (NB*WN)            // 175616 rows

#define LOG2E 1.4426950408889634f

typedef unsigned long long ull_t;

// ---- packed f32x2 helpers ---------------------------------------------------
__device__ __forceinline__ ull_t dup2(float a) {
    ull_t r; asm("mov.b64 %0, {%1, %1};" : "=l"(r) : "f"(a)); return r;
}
__device__ __forceinline__ ull_t fma2(ull_t a, ull_t b, ull_t c) {
    ull_t d; asm("fma.rn.f32x2 %0, %1, %2, %3;" : "=l"(d) : "l"(a), "l"(b), "l"(c)); return d;
}
__device__ __forceinline__ ull_t add2(ull_t a, ull_t b) {
    ull_t d; asm("add.rn.f32x2 %0, %1, %2;" : "=l"(d) : "l"(a), "l"(b)); return d;
}
__device__ __forceinline__ ull_t mul2(ull_t a, ull_t b) {
    ull_t d; asm("mul.rn.f32x2 %0, %1, %2;" : "=l"(d) : "l"(a), "l"(b)); return d;
}
__device__ __forceinline__ void unpack2(ull_t v, float& lo, float& hi) {
    asm("mov.b64 {%0, %1}, %2;" : "=f"(lo), "=f"(hi) : "l"(v));
}
__device__ __forceinline__ float ex2f(float x) {
    float r; asm("ex2.approx.ftz.f32 %0, %1;" : "=f"(r) : "f"(x)); return r;
}

// Scratch (static device arrays: allocation-free).
__device__ float g_q[BH*WN*HD];
__device__ float g_k[BH*WN*HD];
__device__ float g_v[BH*WN*HD];
__device__ float g_o[BH*WN*HD];
// Combined (bias-11+mask)*LOG2E, transposed: g_bm[(w*3+h)][j][i].
// Padded 4*WN so the 3-deep prefetch never reads past the end.
__device__ float g_bm[NWIN*NHEADS*WN*WN + 4*WN];

// ---------------------------------------------------------------------------
// Kernel A: qkv = x @ Wqkv^T + bqkv, scattered to g_q/g_k/g_v [B][H][N][32]
// 64 rows/block, 576 threads = 72 colgroups(4c) x 8 rowgroups(8r), row-packed.
// ---------------------------------------------------------------------------
#define QKV_WPAD 292
#define XT_PAD   68
__global__ __launch_bounds__(576) void qkv_kernel(
    const float* __restrict__ x, const float* __restrict__ Wqkv,
    const float* __restrict__ bqkv)
{
    extern __shared__ float sm[];
    float* Wt  = sm;                     // [96][292] : Wt[k][c] = Wqkv[c][k]
    float* xsT = sm + 96*QKV_WPAD;       // [96][68]  : xsT[k][row]
    const int tid = threadIdx.x;

    for (int idx = tid; idx < 288*96; idx += 576) {
        int c = idx / 96, k = idx - c*96;
        Wt[k*QKV_WPAD + c] = Wqkv[idx];
    }
    const int r0 = blockIdx.x * 64;
    for (int idx = tid; idx < 64*96; idx += 576) {
        int row = idx / 96, k = idx - row*96;
        xsT[k*XT_PAD + row] = x[(r0 + row)*96 + k];
    }
    __syncthreads();

    const int cg = tid % 72;
    const int rg = tid / 72;
    const int c0 = cg * 4;
    const int i0 = rg * 8;

    ull_t acc[4][4];
#pragma unroll
    for (int rp = 0; rp < 4; rp++)
#pragma unroll
        for (int c = 0; c < 4; c++) acc[rp][c] = 0ull;

#pragma unroll 4
    for (int k = 0; k < 96; k++) {
        float4 w = *(const float4*)(Wt + k*QKV_WPAD + c0);
        ull_t wd0 = dup2(w.x), wd1 = dup2(w.y), wd2 = dup2(w.z), wd3 = dup2(w.w);
        ulonglong2 xa = *(const ulonglong2*)(xsT + k*XT_PAD + i0);
        ulonglong2 xb = *(const ulonglong2*)(xsT + k*XT_PAD + i0 + 4);
        acc[0][0] = fma2(xa.x, wd0, acc[0][0]);
        acc[0][1] = fma2(xa.x, wd1, acc[0][1]);
        acc[0][2] = fma2(xa.x, wd2, acc[0][2]);
        acc[0][3] = fma2(xa.x, wd3, acc[0][3]);
        acc[1][0] = fma2(xa.y, wd0, acc[1][0]);
        acc[1][1] = fma2(xa.y, wd1, acc[1][1]);
        acc[1][2] = fma2(xa.y, wd2, acc[1][2]);
        acc[1][3] = fma2(xa.y, wd3, acc[1][3]);
        acc[2][0] = fma2(xb.x, wd0, acc[2][0]);
        acc[2][1] = fma2(xb.x, wd1, acc[2][1]);
        acc[2][2] = fma2(xb.x, wd2, acc[2][2]);
        acc[2][3] = fma2(xb.x, wd3, acc[2][3]);
        acc[3][0] = fma2(xb.y, wd0, acc[3][0]);
        acc[3][1] = fma2(xb.y, wd1, acc[3][1]);
        acc[3][2] = fma2(xb.y, wd2, acc[3][2]);
        acc[3][3] = fma2(xb.y, wd3, acc[3][3]);
    }

    float4 bb = *(const float4*)(bqkv + c0);
    const int seg = c0 / 96;              // 0=q 1=k 2=v
    const int cc  = c0 - seg*96;
    const int h   = cc >> 5;
    const int d0  = cc & 31;
    float* dst = (seg == 0) ? g_q : ((seg == 1) ? g_k : g_v);
#pragma unroll
    for (int rp = 0; rp < 4; rp++) {
        float e0[4], e1[4];
#pragma unroll
        for (int c = 0; c < 4; c++) unpack2(acc[rp][c], e0[c], e1[c]);
        int ra = r0 + i0 + 2*rp;
        int ba = ra / WN, na = ra - ba*WN;
        float4 ov;
        ov.x = e0[0]+bb.x; ov.y = e0[1]+bb.y; ov.z = e0[2]+bb.z; ov.w = e0[3]+bb.w;
        *(float4*)(dst + (((ba*NHEADS + h)*WN) + na)*HD + d0) = ov;
        int rb = ra + 1;
        int bb2 = rb / WN, nb = rb - bb2*WN;
        ov.x = e1[0]+bb.x; ov.y = e1[1]+bb.y; ov.z = e1[2]+bb.z; ov.w = e1[3]+bb.w;
        *(float4*)(dst + (((bb2*NHEADS + h)*WN) + nb)*HD + d0) = ov;
    }
}

// ---------------------------------------------------------------------------
// Kernel B: in-place L2-normalize k; normalize+scale q (scale folds in LOG2E).
// ---------------------------------------------------------------------------
__global__ void norm_kernel(const float* __restrict__ logit_scale)
{
    int row = blockIdx.x*256 + threadIdx.x;
    if (row >= BH*WN) return;
    int h = (row / WN) % NHEADS;
    float scale = expf(fminf(logit_scale[h], 4.6051702f)) * LOG2E;
    float4* qp = (float4*)(g_q + (size_t)row*HD);
    float4* kp = (float4*)(g_k + (size_t)row*HD);
    float4 qv[8], kv[8];
    float sq = 0.f, skk = 0.f;
#pragma unroll
    for (int m = 0; m < 8; m++) {
        qv[m] = qp[m]; kv[m] = kp[m];
        sq  += qv[m].x*qv[m].x + qv[m].y*qv[m].y + qv[m].z*qv[m].z + qv[m].w*qv[m].w;
        skk += kv[m].x*kv[m].x + kv[m].y*kv[m].y + kv[m].z*kv[m].z + kv[m].w*kv[m].w;
    }
    float rq = rsqrtf(fmaxf(sq,  1e-24f)) * scale;
    float rk = rsqrtf(fmaxf(skk, 1e-24f));
#pragma unroll
    for (int m = 0; m < 8; m++) {
        float4 a = qv[m], c = kv[m];
        a.x *= rq; a.y *= rq; a.z *= rq; a.w *= rq;
        c.x *= rk; c.y *= rk; c.z *= rk; c.w *= rk;
        qp[m] = a; kp[m] = c;
    }
}

// ---------------------------------------------------------------------------
// Kernel C: build combined transposed bias+mask:
//   g_bm[(w*3+h)][j][i] = (bias_table[rpi[i][j]][h] - 11 + mask[w][i][j])*LOG2E
// Tiled transpose: reads coalesced over j, writes coalesced over i.
// ---------------------------------------------------------------------------
__global__ void prep_kernel(const float* __restrict__ mask,
                            const float* __restrict__ bias_table,
                            const int* __restrict__ rpi)
{
    __shared__ float tile[32][33];
    const int j0 = blockIdx.x*32;
    const int i0 = blockIdx.y*32;
    const int z  = blockIdx.z;            // slice = w*3 + h
    const int w  = z / NHEADS;
    const int h  = z - w*NHEADS;
    const int tx = threadIdx.x, ty = threadIdx.y;
    const float* msrc = mask + (size_t)w*WN*WN;
#pragma unroll
    for (int s = 0; s < 32; s += 8) {
        int i = i0 + ty + s, j = j0 + tx;
        float v = 0.f;
        if (i < WN && j < WN) {
            v = (bias_table[rpi[i*WN + j]*NHEADS + h] - 11.0f + msrc[i*WN + j]) * LOG2E;
        }
        tile[ty+s][tx] = v;
    }
    __syncthreads();
    float* dst = g_bm + (size_t)z*WN*WN;
#pragma unroll
    for (int s = 0; s < 32; s += 8) {
        int j = j0 + ty + s, i = i0 + tx;
        if (i < WN && j < WN) dst[j*WN + i] = tile[tx][ty+s];
    }
}

// ---------------------------------------------------------------------------
// Kernel D: fused attention per (window, head). 192 threads, 2 query rows each.
// Fixed softmax max (folded into g_bm) -> no rescaling. Combined bias+mask
// stream prefetched 3 iterations deep; next-j score overlaps EX2 + PV.
// ---------------------------------------------------------------------------
#define SCORE(JJ, S0, S1) do {                                            \
    const ulonglong2* kp_ = (const ulonglong2*)(sK + (JJ)*HD);            \
    ull_t a0_ = 0ull, a1_ = 0ull, b0_ = 0ull, b1_ = 0ull;                 \
    _Pragma("unroll")                                                     \
    for (int m_ = 0; m_ < 8; m_++) {                                      \
        ulonglong2 kk_ = kp_[m_];                                         \
        a0_ = fma2(q0p[2*m_],   kk_.x, a0_);                              \
        a1_ = fma2(q0p[2*m_+1], kk_.y, a1_);                              \
        b0_ = fma2(q1p[2*m_],   kk_.x, b0_);                              \
        b1_ = fma2(q1p[2*m_+1], kk_.y, b1_);                              \
    }                                                                     \
    a0_ = add2(a0_, a1_);  b0_ = add2(b0_, b1_);                          \
    float lo_, hi_;                                                       \
    unpack2(a0_, lo_, hi_);  (S0) = lo_ + hi_;                            \
    unpack2(b0_, lo_, hi_);  (S1) = lo_ + hi_;                            \
} while (0)

__global__ __launch_bounds__(192, 2) void attn_kernel()
{
    extern __shared__ float sm[];
    float* sK = sm;                 // [343][32]
    float* sV = sm + WN*HD;         // [343][32]
    const int t  = threadIdx.x;
    const int bh = blockIdx.x;
    const int b  = bh / NHEADS;
    const int h  = bh - b*NHEADS;
    const int w  = b & (NWIN - 1);
    const float* qb = g_q + (size_t)bh*WN*HD;
    const float* kb = g_k + (size_t)bh*WN*HD;
    const float* vb = g_v + (size_t)bh*WN*HD;

    for (int idx = t; idx < WN*HD/4; idx += 192) {
        ((float4*)sK)[idx] = ((const float4*)kb)[idx];
        ((float4*)sV)[idx] = ((const float4*)vb)[idx];
    }

    const int i0 = t;
    const int i1 = t + 192;
    const bool a1 = (i1 < WN);
    const int i1c = a1 ? i1 : 0;

    ull_t q0p[16], q1p[16];
#pragma unroll
    for (int m = 0; m < 8; m++) {
        ulonglong2 v0 = ((const ulonglong2*)(qb + i0*HD))[m];
        q0p[2*m] = v0.x; q0p[2*m+1] = v0.y;
        ulonglong2 v1 = ((const ulonglong2*)(qb + i1c*HD))[m];
        q1p[2*m] = v1.x; q1p[2*m+1] = v1.y;
    }
    __syncthreads();

    const float* bm_p = g_bm + (size_t)(w*NHEADS + h)*WN*WN;

    ull_t o0p[16], o1p[16];
#pragma unroll
    for (int m = 0; m < 16; m++) { o0p[m] = 0ull; o1p[m] = 0ull; }
    float l0 = 0.f, l1 = 0.f;

    // 3-deep rolling prefetch of combined bias+mask (array tail-padded)
    float A0 = __ldg(bm_p + i0),        A1 = __ldg(bm_p + i1c);
    float B0 = __ldg(bm_p + WN + i0),   B1 = __ldg(bm_p + WN + i1c);
    float C0 = __ldg(bm_p + 2*WN + i0), C1 = __ldg(bm_p + 2*WN + i1c);
    const float* pp = bm_p + 3*WN;

    float s0, s1;
    SCORE(0, s0, s1);

    for (int j = 0; j < WN; j++) {
        int jn = (j + 1 < WN) ? (j + 1) : 0;
        float p0 = ex2f(s0 + A0);
        float p1 = ex2f(s1 + A1);
        A0 = B0; A1 = B1; B0 = C0; B1 = C1;
        C0 = __ldg(pp + i0); C1 = __ldg(pp + i1c);
        pp += WN;
        // next score: independent of p -> overlaps EX2 latency
        float ns0, ns1;
        SCORE(jn, ns0, ns1);
        l0 += p0; l1 += p1;
        ull_t pd0 = dup2(p0), pd1 = dup2(p1);
        const ulonglong2* vp = (const ulonglong2*)(sV + j*HD);
#pragma unroll
        for (int m = 0; m < 8; m++) {
            ulonglong2 vv = vp[m];
            o0p[2*m]   = fma2(pd0, vv.x, o0p[2*m]);
            o0p[2*m+1] = fma2(pd0, vv.y, o0p[2*m+1]);
            o1p[2*m]   = fma2(pd1, vv.x, o1p[2*m]);
            o1p[2*m+1] = fma2(pd1, vv.y, o1p[2*m+1]);
        }
        s0 = ns0; s1 = ns1;
    }

    float* ob = g_o + (size_t)bh*WN*HD;
    {
        ull_t invd = dup2(1.f / l0);
#pragma unroll
        for (int m = 0; m < 8; m++) {
            ulonglong2 r;
            r.x = mul2(o0p[2*m],   invd);
            r.y = mul2(o0p[2*m+1], invd);
            ((ulonglong2*)(ob + i0*HD))[m] = r;
        }
    }
    if (a1) {
        ull_t invd = dup2(1.f / l1);
#pragma unroll
        for (int m = 0; m < 8; m++) {
            ulonglong2 r;
            r.x = mul2(o1p[2*m],   invd);
            r.y = mul2(o1p[2*m+1], invd);
            ((ulonglong2*)(ob + i1*HD))[m] = r;
        }
    }
}

// ---------------------------------------------------------------------------
// Kernel E: out = gathered(g_o) @ Wproj^T + bproj (row-packed f32x2)
// ---------------------------------------------------------------------------
#define PJ_WPAD 100
__global__ __launch_bounds__(192) void proj_kernel(
    const float* __restrict__ Wproj, const float* __restrict__ bproj,
    float* __restrict__ out)
{
    extern __shared__ float sm[];
    float* Wt  = sm;                   // [96][100]
    float* xsT = sm + 96*PJ_WPAD;      // [96][68] : xsT[f][row]
    const int tid = threadIdx.x;
    for (int idx = tid; idx < 96*96; idx += 192) {
        int c = idx / 96, k = idx - c*96;
        Wt[k*PJ_WPAD + c] = Wproj[idx];
    }
    const int r0 = blockIdx.x*64;
    for (int idx = tid; idx < 64*96; idx += 192) {
        int row = idx / 96, f = idx - row*96;
        int r = r0 + row;
        int b = r / WN, n = r - b*WN;
        int h = f >> 5, d = f & 31;
        xsT[f*XT_PAD + row] = g_o[(((b*NHEADS + h)*WN) + n)*HD + d];
    }
    __syncthreads();

    const int cg = tid % 24, rg = tid / 24;
    const int c0 = cg*4;
    const int i0 = rg*8;

    ull_t acc[4][4];
#pragma unroll
    for (int rp = 0; rp < 4; rp++)
#pragma unroll
        for (int c = 0; c < 4; c++) acc[rp][c] = 0ull;

#pragma unroll 4
    for (int k = 0; k < 96; k++) {
        float4 w = *(const float4*)(Wt + k*PJ_WPAD + c0);
        ull_t wd0 = dup2(w.x), wd1 = dup2(w.y), wd2 = dup2(w.z), wd3 = dup2(w.w);
        ulonglong2 xa = *(const ulonglong2*)(xsT + k*XT_PAD + i0);
        ulonglong2 xb = *(const ulonglong2*)(xsT + k*XT_PAD + i0 + 4);
        acc[0][0] = fma2(xa.x, wd0, acc[0][0]);
        acc[0][1] = fma2(xa.x, wd1, acc[0][1]);
        acc[0][2] = fma2(xa.x, wd2, acc[0][2]);
        acc[0][3] = fma2(xa.x, wd3, acc[0][3]);
        acc[1][0] = fma2(xa.y, wd0, acc[1][0]);
        acc[1][1] = fma2(xa.y, wd1, acc[1][1]);
        acc[1][2] = fma2(xa.y, wd2, acc[1][2]);
        acc[1][3] = fma2(xa.y, wd3, acc[1][3]);
        acc[2][0] = fma2(xb.x, wd0, acc[2][0]);
        acc[2][1] = fma2(xb.x, wd1, acc[2][1]);
        acc[2][2] = fma2(xb.x, wd2, acc[2][2]);
        acc[2][3] = fma2(xb.x, wd3, acc[2][3]);
        acc[3][0] = fma2(xb.y, wd0, acc[3][0]);
        acc[3][1] = fma2(xb.y, wd1, acc[3][1]);
        acc[3][2] = fma2(xb.y, wd2, acc[3][2]);
        acc[3][3] = fma2(xb.y, wd3, acc[3][3]);
    }

    float4 bb = *(const float4*)(bproj + c0);
#pragma unroll
    for (int rp = 0; rp < 4; rp++) {
        float e0[4], e1[4];
#pragma unroll
        for (int c = 0; c < 4; c++) unpack2(acc[rp][c], e0[c], e1[c]);
        int ra = r0 + i0 + 2*rp;
        float4 ov;
        ov.x = e0[0]+bb.x; ov.y = e0[1]+bb.y; ov.z = e0[2]+bb.z; ov.w = e0[3]+bb.w;
        *(float4*)(out + (size_t)ra*CDIM + c0) = ov;
        ov.x = e1[0]+bb.x; ov.y = e1[1]+bb.y; ov.z = e1[2]+bb.z; ov.w = e1[3]+bb.w;
        *(float4*)(out + (size_t)(ra+1)*CDIM + c0) = ov;
    }
}

// ---------------------------------------------------------------------------
extern "C" void kernel_launch(void* const* d_in, const int* in_sizes, int n_in,
                              void* d_out, int out_size)
{
    (void)in_sizes; (void)n_in; (void)out_size;
    const float* x           = (const float*)d_in[0];
    const float* mask        = (const float*)d_in[1];
    const float* Wqkv        = (const float*)d_in[2];
    const float* bqkv        = (const float*)d_in[3];
    const float* Wproj       = (const float*)d_in[4];
    const float* bproj       = (const float*)d_in[5];
    const float* logit_scale = (const float*)d_in[6];
    const float* bias_table  = (const float*)d_in[7];
    const int*   rpi         = (const int*)d_in[8];
    float* out = (float*)d_out;

    const int smA = (96*QKV_WPAD + 96*XT_PAD) * 4;   // 138240 B
    const int smD = 2*WN*HD*4;                        // 87808 B
    const int smE = (96*PJ_WPAD + 96*XT_PAD) * 4;    // 64512 B
    cudaFuncSetAttribute(qkv_kernel,  cudaFuncAttributeMaxDynamicSharedMemorySize, smA);
    cudaFuncSetAttribute(attn_kernel, cudaFuncAttributeMaxDynamicSharedMemorySize, smD);
    cudaFuncSetAttribute(proj_kernel, cudaFuncAttributeMaxDynamicSharedMemorySize, smE);

    qkv_kernel<<<RTOT/64, 576, smA>>>(x, Wqkv, bqkv);
    prep_kernel<<<dim3(11, 11, NWIN*NHEADS), dim3(32, 8)>>>(mask, bias_table, rpi);
    norm_kernel<<<(BH*WN + 255)/256, 256>>>(logit_scale);
    attn_kernel<<<BH, 192, smD>>>();
    proj_kernel<<<RTOT/64, 192, smE>>>(Wproj, bproj, out);
}